// round 8
// baseline (speedup 1.0000x reference)
#include <cuda_runtime.h>

// GNNPolicy: 2-layer GCN + node logits head + graph mean-pool value head.
// Inputs (metadata order): x[N,128] f32, edge_index[2,E] int32 (JAX x64 off!),
//   batch[N] int32, W1[128,64], b1[64], W2[64,64], b2[64], Wa[64,1], ba[1],
//   Wc[64,1], bc[1]
// Output: concat(action_logits[N], value[G]) as float32, out_size = N + G.

#define HD 64
#define MAXN 100000
#define MAXG 64

// ---- scratch (static device arrays; 16B-aligned for float4 ld/st) ----
__device__ __align__(16) float g_deg[MAXN];
__device__ __align__(16) float g_dinv[MAXN];
__device__ __align__(16) float g_T[(size_t)MAXN * HD];    // linear transform output
__device__ __align__(16) float g_AGG[(size_t)MAXN * HD];  // aggregation accumulator
__device__ __align__(16) float g_H[(size_t)MAXN * HD];    // relu(layer1) = input to layer2
__device__ __align__(16) float g_pooled[MAXG * HD];
__device__ __align__(16) float g_counts[MAXG];

// ---- init: deg = 1 (self loop), pooled/counts = 0 ----
__global__ void k_init(int n) {
    int i = blockIdx.x * blockDim.x + threadIdx.x;
    if (i < n) g_deg[i] = 1.0f;
    if (i < MAXG * HD) g_pooled[i] = 0.0f;
    if (i < MAXG) g_counts[i] = 0.0f;
}

// ---- degree over dst ----
__global__ void k_deg(const int* __restrict__ ei, int E, int n) {
    int e = blockIdx.x * blockDim.x + threadIdx.x;
    if (e < E) {
        int dst = ei[E + e];
        if ((unsigned)dst < (unsigned)n)            // defensive (dtype sanity)
            atomicAdd(&g_deg[dst], 1.0f);
    }
}

__global__ void k_dinv(int n) {
    int i = blockIdx.x * blockDim.x + threadIdx.x;
    if (i < n) g_dinv[i] = rsqrtf(g_deg[i]);   // deg >= 1 always (self loop)
}

// ---- GEMM: T = X @ W  [n,K]x[K,64]; epilogue: AGG = b + T * dinv^2 (self-loop + bias)
// W transposed into smem (pad 4 floats -> conflict-free 16B smem loads).
// 8 warps/block, 8 rows/warp (64 rows/block). Lane c owns cols {c, c+32}.
template<int K, bool USE_H>
__global__ void k_gemm(const float* __restrict__ Xin, const float* __restrict__ W,
                       const float* __restrict__ b, int n) {
    __shared__ __align__(16) float Wt[HD * (K + 4)];
    const float* X = USE_H ? (const float*)g_H : Xin;

    int tid = threadIdx.x;
    for (int idx = tid; idx < K * HD; idx += 256) {
        int k = idx >> 6, c = idx & 63;          // W row-major [K][64]
        Wt[c * (K + 4) + k] = W[idx];
    }
    __syncthreads();

    int warp = tid >> 5, lane = tid & 31;
    int row0 = blockIdx.x * 64 + warp * 8;
    const float* wt0 = &Wt[lane * (K + 4)];
    const float* wt1 = &Wt[(lane + 32) * (K + 4)];

    const float4* xp[8];
#pragma unroll
    for (int r = 0; r < 8; r++) {
        int rr = row0 + r; if (rr > n - 1) rr = n - 1;    // clamp (safe reads)
        xp[r] = (const float4*)(X + (size_t)rr * K);
    }

    float acc0[8], acc1[8];
#pragma unroll
    for (int r = 0; r < 8; r++) { acc0[r] = 0.0f; acc1[r] = 0.0f; }

#pragma unroll 4
    for (int k = 0; k < K; k += 4) {
        float4 wa = *(const float4*)(wt0 + k);
        float4 wb = *(const float4*)(wt1 + k);
        int k4 = k >> 2;
#pragma unroll
        for (int r = 0; r < 8; r++) {
            float4 xv = xp[r][k4];
            acc0[r] += xv.x * wa.x + xv.y * wa.y + xv.z * wa.z + xv.w * wa.w;
            acc1[r] += xv.x * wb.x + xv.y * wb.y + xv.z * wb.z + xv.w * wb.w;
        }
    }

    float b0 = b[lane], b1 = b[lane + 32];
#pragma unroll
    for (int r = 0; r < 8; r++) {
        int rr = row0 + r;
        if (rr < n) {
            float di = g_dinv[rr];
            float di2 = di * di;
            g_T[(size_t)rr * HD + lane]        = acc0[r];
            g_T[(size_t)rr * HD + lane + 32]   = acc1[r];
            g_AGG[(size_t)rr * HD + lane]      = b0 + acc0[r] * di2;
            g_AGG[(size_t)rr * HD + lane + 32] = b1 + acc1[r] * di2;
        }
    }
}

// ---- edge scatter: AGG[dst] += T[src] * dinv[src]*dinv[dst]
// 16 lanes per edge; lane l owns columns {l, l+16, l+32, l+48}; each atomic
// instruction is coalesced across the 16 lanes (64B segments).
__global__ void k_edge(const int* __restrict__ ei, int E, int n) {
    int tid = blockIdx.x * blockDim.x + threadIdx.x;
    int e = tid >> 4;
    if (e >= E) return;
    int l = tid & 15;
    int src = ei[e];
    int dst = ei[E + e];
    if ((unsigned)src >= (unsigned)n || (unsigned)dst >= (unsigned)n) return;  // defensive
    float w = g_dinv[src] * g_dinv[dst];
    const float* t = g_T + (size_t)src * HD;
    float* a = g_AGG + (size_t)dst * HD;
    atomicAdd(a + l,      t[l]      * w);
    atomicAdd(a + l + 16, t[l + 16] * w);
    atomicAdd(a + l + 32, t[l + 32] * w);
    atomicAdd(a + l + 48, t[l + 48] * w);
}

// ---- relu layer1 -> H ----
__global__ void k_relu(int n16) {
    int i = blockIdx.x * blockDim.x + threadIdx.x;
    if (i < n16) {
        float4 v = ((const float4*)g_AGG)[i];
        v.x = fmaxf(v.x, 0.0f); v.y = fmaxf(v.y, 0.0f);
        v.z = fmaxf(v.z, 0.0f); v.w = fmaxf(v.w, 0.0f);
        ((float4*)g_H)[i] = v;
    }
}

// ---- finalize layer2: relu, logits = h2.Wa + ba, mean-pool scatter
// 16 lanes per node, lane l owns columns {l, l+16, l+32, l+48}.
__global__ void k_final(const int* __restrict__ batch, const float* __restrict__ Wa,
                        const float* __restrict__ ba, float* __restrict__ out, int n) {
    int tid = blockIdx.x * blockDim.x + threadIdx.x;
    int node = tid >> 4;
    if (node >= n) return;
    int l = tid & 15;
    const float* h = g_AGG + (size_t)node * HD;
    float v0 = fmaxf(h[l],      0.0f);
    float v1 = fmaxf(h[l + 16], 0.0f);
    float v2 = fmaxf(h[l + 32], 0.0f);
    float v3 = fmaxf(h[l + 48], 0.0f);
    float s = v0 * Wa[l] + v1 * Wa[l + 16] + v2 * Wa[l + 32] + v3 * Wa[l + 48];
    s += __shfl_xor_sync(0xffffffffu, s, 8);
    s += __shfl_xor_sync(0xffffffffu, s, 4);
    s += __shfl_xor_sync(0xffffffffu, s, 2);
    s += __shfl_xor_sync(0xffffffffu, s, 1);
    int g = batch[node];
    if ((unsigned)g < (unsigned)MAXG) {              // defensive
        float* p = g_pooled + g * HD;
        atomicAdd(p + l,      v0);
        atomicAdd(p + l + 16, v1);
        atomicAdd(p + l + 32, v2);
        atomicAdd(p + l + 48, v3);
        if (l == 0) atomicAdd(&g_counts[g], 1.0f);
    }
    if (l == 0) out[node] = s + ba[0];
}

// ---- value head: value[g] = (pooled[g].Wc)/max(count,1) + bc ----
__global__ void k_value(const float* __restrict__ Wc, const float* __restrict__ bc,
                        float* __restrict__ out, int n) {
    int g = blockIdx.x, lane = threadIdx.x;
    float s = g_pooled[g * HD + lane] * Wc[lane]
            + g_pooled[g * HD + 32 + lane] * Wc[32 + lane];
    s += __shfl_xor_sync(0xffffffffu, s, 16);
    s += __shfl_xor_sync(0xffffffffu, s, 8);
    s += __shfl_xor_sync(0xffffffffu, s, 4);
    s += __shfl_xor_sync(0xffffffffu, s, 2);
    s += __shfl_xor_sync(0xffffffffu, s, 1);
    if (lane == 0)
        out[n + g] = s / fmaxf(g_counts[g], 1.0f) + bc[0];
}

extern "C" void kernel_launch(void* const* d_in, const int* in_sizes, int n_in,
                              void* d_out, int out_size) {
    const float* x     = (const float*)d_in[0];
    const int*   ei    = (const int*)d_in[1];      // int32! (JAX x64 disabled)
    const int*   batch = (const int*)d_in[2];      // int32!
    const float* W1    = (const float*)d_in[3];
    const float* b1    = (const float*)d_in[4];
    const float* W2    = (const float*)d_in[5];
    const float* b2    = (const float*)d_in[6];
    const float* Wa    = (const float*)d_in[7];
    const float* ba    = (const float*)d_in[8];
    const float* Wc    = (const float*)d_in[9];
    const float* bc    = (const float*)d_in[10];
    float* out = (float*)d_out;

    int n = in_sizes[2];
    int E = in_sizes[1] / 2;
    int G = out_size - n;   // = 64

    k_init<<<(n + 255) / 256, 256>>>(n);
    k_deg<<<(E + 255) / 256, 256>>>(ei, E, n);
    k_dinv<<<(n + 255) / 256, 256>>>(n);

    // layer 1
    k_gemm<128, false><<<(n + 63) / 64, 256>>>(x, W1, b1, n);
    k_edge<<<(int)(((long long)E * 16 + 255) / 256), 256>>>(ei, E, n);
    k_relu<<<(n * 16 + 255) / 256, 256>>>(n * 16);

    // layer 2
    k_gemm<64, true><<<(n + 63) / 64, 256>>>(x /*unused*/, W2, b2, n);
    k_edge<<<(int)(((long long)E * 16 + 255) / 256), 256>>>(ei, E, n);

    // heads
    k_final<<<(n * 16 + 255) / 256, 256>>>(batch, Wa, ba, out, n);
    if (G > 0) k_value<<<G, 32>>>(Wc, bc, out, n);
}

// round 9
// speedup vs baseline: 1.2326x; 1.2326x over previous
#include <cuda_runtime.h>

// GNNPolicy: 2-layer GCN + node logits head + graph mean-pool value head.
// Inputs (metadata order): x[N,128] f32, edge_index[2,E] int32, batch[N] int32,
//   W1[128,64], b1[64], W2[64,64], b2[64], Wa[64,1], ba[1], Wc[64,1], bc[1]
// Output: concat(action_logits[N], value[G]) as float32, out_size = N + G.

#define HD 64
#define MAXN 100000
#define MAXG 64

// ---- scratch (static device arrays; 16B-aligned for float4 ld/st + v4 RED) ----
__device__ __align__(16) float g_deg[MAXN];
__device__ __align__(16) float g_dinv[MAXN];
__device__ __align__(16) float g_T[(size_t)MAXN * HD];    // linear transform output
__device__ __align__(16) float g_AGG[(size_t)MAXN * HD];  // aggregation accumulator
__device__ __align__(16) float g_pooled[MAXG * HD];
__device__ __align__(16) float g_counts[MAXG];

__device__ __forceinline__ void atomic_add_v4(float4* addr, float4 v) {
#if defined(__CUDA_ARCH__) && (__CUDA_ARCH__ >= 900)
    atomicAdd(addr, v);          // RED.ADD.F32x4 on sm_90+
#else
    float* a = (float*)addr;
    atomicAdd(a + 0, v.x); atomicAdd(a + 1, v.y);
    atomicAdd(a + 2, v.z); atomicAdd(a + 3, v.w);
#endif
}

// ---- init: deg = 1 (self loop), pooled/counts = 0 ----
__global__ void k_init(int n) {
    int i = blockIdx.x * blockDim.x + threadIdx.x;
    if (i < n) g_deg[i] = 1.0f;
    if (i < MAXG * HD) g_pooled[i] = 0.0f;
    if (i < MAXG) g_counts[i] = 0.0f;
}

// ---- degree over dst ----
__global__ void k_deg(const int* __restrict__ ei, int E, int n) {
    int e = blockIdx.x * blockDim.x + threadIdx.x;
    if (e < E) {
        int dst = ei[E + e];
        if ((unsigned)dst < (unsigned)n)
            atomicAdd(&g_deg[dst], 1.0f);
    }
}

__global__ void k_dinv(int n) {
    int i = blockIdx.x * blockDim.x + threadIdx.x;
    if (i < n) g_dinv[i] = rsqrtf(g_deg[i]);   // deg >= 1 always (self loop)
}

// ---- GEMM: T = act(X) @ W  [n,K]x[K,64]; epilogue: AGG = b + T * dinv^2
// Layer 2 (USE_AGG): X = g_AGG with inline ReLU (fused; row-local so the
// read-then-overwrite of g_AGG is safe within the owning warp).
// W transposed into smem (pad 4 floats -> conflict-free 16B smem loads).
// 8 warps/block, 8 rows/warp (64 rows/block). Lane c owns cols {c, c+32}.
template<int K, bool USE_AGG>
__global__ void k_gemm(const float* __restrict__ Xin, const float* __restrict__ W,
                       const float* __restrict__ b, int n) {
    __shared__ __align__(16) float Wt[HD * (K + 4)];
    const float* X = USE_AGG ? (const float*)g_AGG : Xin;

    int tid = threadIdx.x;
    for (int idx = tid; idx < K * HD; idx += 256) {
        int k = idx >> 6, c = idx & 63;          // W row-major [K][64]
        Wt[c * (K + 4) + k] = W[idx];
    }
    __syncthreads();

    int warp = tid >> 5, lane = tid & 31;
    int row0 = blockIdx.x * 64 + warp * 8;
    const float* wt0 = &Wt[lane * (K + 4)];
    const float* wt1 = &Wt[(lane + 32) * (K + 4)];

    const float4* xp[8];
#pragma unroll
    for (int r = 0; r < 8; r++) {
        int rr = row0 + r; if (rr > n - 1) rr = n - 1;    // clamp (safe reads)
        xp[r] = (const float4*)(X + (size_t)rr * K);
    }

    float acc0[8], acc1[8];
#pragma unroll
    for (int r = 0; r < 8; r++) { acc0[r] = 0.0f; acc1[r] = 0.0f; }

#pragma unroll 4
    for (int k = 0; k < K; k += 4) {
        float4 wa = *(const float4*)(wt0 + k);
        float4 wb = *(const float4*)(wt1 + k);
        int k4 = k >> 2;
#pragma unroll
        for (int r = 0; r < 8; r++) {
            float4 xv = xp[r][k4];
            if (USE_AGG) {                        // fused ReLU on layer-2 input
                xv.x = fmaxf(xv.x, 0.0f); xv.y = fmaxf(xv.y, 0.0f);
                xv.z = fmaxf(xv.z, 0.0f); xv.w = fmaxf(xv.w, 0.0f);
            }
            acc0[r] += xv.x * wa.x + xv.y * wa.y + xv.z * wa.z + xv.w * wa.w;
            acc1[r] += xv.x * wb.x + xv.y * wb.y + xv.z * wb.z + xv.w * wb.w;
        }
    }

    float b0 = b[lane], b1 = b[lane + 32];
#pragma unroll
    for (int r = 0; r < 8; r++) {
        int rr = row0 + r;
        if (rr < n) {
            float di = g_dinv[rr];
            float di2 = di * di;
            g_T[(size_t)rr * HD + lane]        = acc0[r];
            g_T[(size_t)rr * HD + lane + 32]   = acc1[r];
            g_AGG[(size_t)rr * HD + lane]      = b0 + acc0[r] * di2;
            g_AGG[(size_t)rr * HD + lane + 32] = b1 + acc1[r] * di2;
        }
    }
}

// ---- edge scatter: AGG[dst] += T[src] * dinv[src]*dinv[dst]
// 16 lanes per edge; lane l owns float4 chunk l (one v4 RED per lane).
__global__ void k_edge(const int* __restrict__ ei, int E, int n) {
    int tid = blockIdx.x * blockDim.x + threadIdx.x;
    int e = tid >> 4;
    if (e >= E) return;
    int l = tid & 15;
    int src = ei[e];
    int dst = ei[E + e];
    if ((unsigned)src >= (unsigned)n || (unsigned)dst >= (unsigned)n) return;
    float w = g_dinv[src] * g_dinv[dst];
    float4 t = ((const float4*)(g_T + (size_t)src * HD))[l];
    t.x *= w; t.y *= w; t.z *= w; t.w *= w;
    atomic_add_v4((float4*)(g_AGG + (size_t)dst * HD) + l, t);
}

// ---- finalize layer2: relu, logits = h2.Wa + ba, mean-pool scatter
// 16 lanes per node, lane l owns float4 chunk l.
__global__ void k_final(const int* __restrict__ batch, const float* __restrict__ Wa,
                        const float* __restrict__ ba, float* __restrict__ out, int n) {
    int tid = blockIdx.x * blockDim.x + threadIdx.x;
    int node = tid >> 4;
    if (node >= n) return;
    int l = tid & 15;
    float4 v = ((const float4*)(g_AGG + (size_t)node * HD))[l];
    v.x = fmaxf(v.x, 0.0f); v.y = fmaxf(v.y, 0.0f);
    v.z = fmaxf(v.z, 0.0f); v.w = fmaxf(v.w, 0.0f);
    float4 wa = ((const float4*)Wa)[l];
    float s = v.x * wa.x + v.y * wa.y + v.z * wa.z + v.w * wa.w;
    s += __shfl_xor_sync(0xffffffffu, s, 8);
    s += __shfl_xor_sync(0xffffffffu, s, 4);
    s += __shfl_xor_sync(0xffffffffu, s, 2);
    s += __shfl_xor_sync(0xffffffffu, s, 1);
    int g = batch[node];
    if ((unsigned)g < (unsigned)MAXG) {
        atomic_add_v4((float4*)(g_pooled + g * HD) + l, v);
        if (l == 0) atomicAdd(&g_counts[g], 1.0f);
    }
    if (l == 0) out[node] = s + ba[0];
}

// ---- value head: value[g] = (pooled[g].Wc)/max(count,1) + bc ----
__global__ void k_value(const float* __restrict__ Wc, const float* __restrict__ bc,
                        float* __restrict__ out, int n) {
    int g = blockIdx.x, lane = threadIdx.x;
    float s = g_pooled[g * HD + lane] * Wc[lane]
            + g_pooled[g * HD + 32 + lane] * Wc[32 + lane];
    s += __shfl_xor_sync(0xffffffffu, s, 16);
    s += __shfl_xor_sync(0xffffffffu, s, 8);
    s += __shfl_xor_sync(0xffffffffu, s, 4);
    s += __shfl_xor_sync(0xffffffffu, s, 2);
    s += __shfl_xor_sync(0xffffffffu, s, 1);
    if (lane == 0)
        out[n + g] = s / fmaxf(g_counts[g], 1.0f) + bc[0];
}

extern "C" void kernel_launch(void* const* d_in, const int* in_sizes, int n_in,
                              void* d_out, int out_size) {
    const float* x     = (const float*)d_in[0];
    const int*   ei    = (const int*)d_in[1];      // int32 (JAX x64 disabled)
    const int*   batch = (const int*)d_in[2];      // int32
    const float* W1    = (const float*)d_in[3];
    const float* b1    = (const float*)d_in[4];
    const float* W2    = (const float*)d_in[5];
    const float* b2    = (const float*)d_in[6];
    const float* Wa    = (const float*)d_in[7];
    const float* ba    = (const float*)d_in[8];
    const float* Wc    = (const float*)d_in[9];
    const float* bc    = (const float*)d_in[10];
    float* out = (float*)d_out;

    int n = in_sizes[2];
    int E = in_sizes[1] / 2;
    int G = out_size - n;   // = 64

    k_init<<<(n + 255) / 256, 256>>>(n);
    k_deg<<<(E + 255) / 256, 256>>>(ei, E, n);
    k_dinv<<<(n + 255) / 256, 256>>>(n);

    // layer 1
    k_gemm<128, false><<<(n + 63) / 64, 256>>>(x, W1, b1, n);
    k_edge<<<(int)(((long long)E * 16 + 255) / 256), 256>>>(ei, E, n);

    // layer 2 (ReLU fused into input load; reads+overwrites g_AGG row-locally)
    k_gemm<64, true><<<(n + 63) / 64, 256>>>(x /*unused*/, W2, b2, n);
    k_edge<<<(int)(((long long)E * 16 + 255) / 256), 256>>>(ei, E, n);

    // heads
    k_final<<<(n * 16 + 255) / 256, 256>>>(batch, Wa, ba, out, n);
    if (G > 0) k_value<<<G, 32>>>(Wc, bc, out, n);
}

// round 10
// speedup vs baseline: 1.5605x; 1.2660x over previous
#include <cuda_runtime.h>

// GNNPolicy: 2-layer GCN + node logits head + graph mean-pool value head.
// CSR-gather formulation: build dst-CSR once per launch, then aggregation is
// a pure gather (no float atomics in the hot path).
// Inputs (metadata order): x[N,128] f32, edge_index[2,E] int32, batch[N] int32,
//   W1[128,64], b1[64], W2[64,64], b2[64], Wa[64,1], ba[1], Wc[64,1], bc[1]
// Output: concat(action_logits[N], value[G]) as float32, out_size = N + G.

#define HD 64
#define MAXN 100000
#define MAXE 1600000
#define MAXG 64
#define SCB  1024   // scan block width

// ---- scratch ----
__device__ __align__(16) int   g_cnt[MAXN];      // in-degree (dst), no self-loop
__device__ __align__(16) int   g_rowptr[MAXN];   // CSR row starts
__device__ __align__(16) int   g_cursor[MAXN];   // fill cursors
__device__ __align__(16) int   g_csrc[MAXE];     // CSR: src per (dst-sorted) edge
__device__ __align__(16) int   g_bsum[256];      // scan block sums
__device__ __align__(16) float g_dinv[MAXN];
__device__ __align__(16) float g_T[(size_t)MAXN * HD];    // Tp = (X@W) * dinv[row]
__device__ __align__(16) float g_AGG[(size_t)MAXN * HD];  // aggregated features
__device__ __align__(16) float g_pooled[MAXG * HD];
__device__ __align__(16) float g_counts[MAXG];

__device__ __forceinline__ void atomic_add_v4(float4* addr, float4 v) {
#if defined(__CUDA_ARCH__) && (__CUDA_ARCH__ >= 900)
    atomicAdd(addr, v);
#else
    float* a = (float*)addr;
    atomicAdd(a + 0, v.x); atomicAdd(a + 1, v.y);
    atomicAdd(a + 2, v.z); atomicAdd(a + 3, v.w);
#endif
}

// ---- zero: cnt, pooled, counts ----
__global__ void k_zero(int n) {
    int i = blockIdx.x * blockDim.x + threadIdx.x;
    if (i < n) g_cnt[i] = 0;
    if (i < MAXG * HD) g_pooled[i] = 0.0f;
    if (i < MAXG) g_counts[i] = 0.0f;
}

// ---- histogram over dst ----
__global__ void k_hist(const int* __restrict__ ei, int E, int n) {
    int e = blockIdx.x * blockDim.x + threadIdx.x;
    if (e < E) {
        int dst = ei[E + e];
        if ((unsigned)dst < (unsigned)n) atomicAdd(&g_cnt[dst], 1);
    }
}

// ---- scan level 1: per-block exclusive scan of cnt -> rowptr(local), block totals
__global__ void k_scan1(int n) {
    __shared__ int s[SCB];
    int t = threadIdx.x;
    int i = blockIdx.x * SCB + t;
    int v = (i < n) ? g_cnt[i] : 0;
    s[t] = v;
    __syncthreads();
#pragma unroll
    for (int off = 1; off < SCB; off <<= 1) {
        int x = (t >= off) ? s[t - off] : 0;
        __syncthreads();
        s[t] += x;
        __syncthreads();
    }
    if (i < n) g_rowptr[i] = s[t] - v;          // local exclusive
    if (t == SCB - 1) g_bsum[blockIdx.x] = s[t]; // block total
}

// ---- scan level 2: exclusive scan of block totals (single block, 256 threads)
__global__ void k_scan2(int nb) {
    __shared__ int s[256];
    int t = threadIdx.x;
    int v = (t < nb) ? g_bsum[t] : 0;
    s[t] = v;
    __syncthreads();
#pragma unroll
    for (int off = 1; off < 256; off <<= 1) {
        int x = (t >= off) ? s[t - off] : 0;
        __syncthreads();
        s[t] += x;
        __syncthreads();
    }
    if (t < nb) g_bsum[t] = s[t] - v;           // exclusive
}

// ---- scan level 3: apply block offsets; init cursor; dinv = rsqrt(deg+1)
__global__ void k_scan3(int n) {
    int i = blockIdx.x * blockDim.x + threadIdx.x;
    if (i < n) {
        int rp = g_rowptr[i] + g_bsum[i >> 10];
        g_rowptr[i] = rp;
        g_cursor[i] = rp;
        g_dinv[i]   = rsqrtf((float)(g_cnt[i] + 1));
    }
}

// ---- fill CSR: csrc[pos] = src, pos from per-dst cursor ----
__global__ void k_fill(const int* __restrict__ ei, int E, int n) {
    int e = blockIdx.x * blockDim.x + threadIdx.x;
    if (e < E) {
        int src = ei[e];
        int dst = ei[E + e];
        if ((unsigned)src < (unsigned)n && (unsigned)dst < (unsigned)n) {
            int pos = atomicAdd(&g_cursor[dst], 1);
            g_csrc[pos] = src;
        }
    }
}

// ---- GEMM: Tp = act(X) @ W * dinv[row]   [n,K]x[K,64]
// Layer 2 (USE_AGG): X = relu(g_AGG) fused on load.
// 8 warps/block, 8 rows/warp. Lane c owns cols {c, c+32}.
template<int K, bool USE_AGG>
__global__ void k_gemm(const float* __restrict__ Xin, const float* __restrict__ W,
                       int n) {
    __shared__ __align__(16) float Wt[HD * (K + 4)];
    const float* X = USE_AGG ? (const float*)g_AGG : Xin;

    int tid = threadIdx.x;
    for (int idx = tid; idx < K * HD; idx += 256) {
        int k = idx >> 6, c = idx & 63;          // W row-major [K][64]
        Wt[c * (K + 4) + k] = W[idx];
    }
    __syncthreads();

    int warp = tid >> 5, lane = tid & 31;
    int row0 = blockIdx.x * 64 + warp * 8;
    const float* wt0 = &Wt[lane * (K + 4)];
    const float* wt1 = &Wt[(lane + 32) * (K + 4)];

    const float4* xp[8];
#pragma unroll
    for (int r = 0; r < 8; r++) {
        int rr = row0 + r; if (rr > n - 1) rr = n - 1;    // clamp (safe reads)
        xp[r] = (const float4*)(X + (size_t)rr * K);
    }

    float acc0[8], acc1[8];
#pragma unroll
    for (int r = 0; r < 8; r++) { acc0[r] = 0.0f; acc1[r] = 0.0f; }

#pragma unroll 4
    for (int k = 0; k < K; k += 4) {
        float4 wa = *(const float4*)(wt0 + k);
        float4 wb = *(const float4*)(wt1 + k);
        int k4 = k >> 2;
#pragma unroll
        for (int r = 0; r < 8; r++) {
            float4 xv = xp[r][k4];
            if (USE_AGG) {
                xv.x = fmaxf(xv.x, 0.0f); xv.y = fmaxf(xv.y, 0.0f);
                xv.z = fmaxf(xv.z, 0.0f); xv.w = fmaxf(xv.w, 0.0f);
            }
            acc0[r] += xv.x * wa.x + xv.y * wa.y + xv.z * wa.z + xv.w * wa.w;
            acc1[r] += xv.x * wb.x + xv.y * wb.y + xv.z * wb.z + xv.w * wb.w;
        }
    }

#pragma unroll
    for (int r = 0; r < 8; r++) {
        int rr = row0 + r;
        if (rr < n) {
            float di = g_dinv[rr];
            g_T[(size_t)rr * HD + lane]      = acc0[r] * di;
            g_T[(size_t)rr * HD + lane + 32] = acc1[r] * di;
        }
    }
}

// ---- gather: AGG[v] = b + dinv[v] * (Tp[v] + sum_{src in row v} Tp[src])
// 16 lanes per node, lane l owns float4 chunk l. Index prefetch pipeline.
__global__ void k_gather(const float* __restrict__ b, int n) {
    int tid = blockIdx.x * blockDim.x + threadIdx.x;
    int v = tid >> 4;
    if (v >= n) return;
    int l = tid & 15;
    int start = g_rowptr[v];
    int cnt   = g_cnt[v];
    float4 s = ((const float4*)(g_T + (size_t)v * HD))[l];   // self loop (Tp[v])
    int u = (cnt > 0) ? g_csrc[start] : 0;
    for (int j = 0; j < cnt; j++) {
        int un = (j + 1 < cnt) ? g_csrc[start + j + 1] : 0;  // prefetch next idx
        float4 t = ((const float4*)(g_T + (size_t)u * HD))[l];
        s.x += t.x; s.y += t.y; s.z += t.z; s.w += t.w;
        u = un;
    }
    float dv = g_dinv[v];
    float4 bb = ((const float4*)b)[l];
    float4 o;
    o.x = bb.x + dv * s.x; o.y = bb.y + dv * s.y;
    o.z = bb.z + dv * s.z; o.w = bb.w + dv * s.w;
    ((float4*)(g_AGG + (size_t)v * HD))[l] = o;
}

// ---- finalize: relu, logits = h2.Wa + ba, mean-pool scatter ----
__global__ void k_final(const int* __restrict__ batch, const float* __restrict__ Wa,
                        const float* __restrict__ ba, float* __restrict__ out, int n) {
    int tid = blockIdx.x * blockDim.x + threadIdx.x;
    int node = tid >> 4;
    if (node >= n) return;
    int l = tid & 15;
    float4 v = ((const float4*)(g_AGG + (size_t)node * HD))[l];
    v.x = fmaxf(v.x, 0.0f); v.y = fmaxf(v.y, 0.0f);
    v.z = fmaxf(v.z, 0.0f); v.w = fmaxf(v.w, 0.0f);
    float4 wa = ((const float4*)Wa)[l];
    float s = v.x * wa.x + v.y * wa.y + v.z * wa.z + v.w * wa.w;
    s += __shfl_xor_sync(0xffffffffu, s, 8);
    s += __shfl_xor_sync(0xffffffffu, s, 4);
    s += __shfl_xor_sync(0xffffffffu, s, 2);
    s += __shfl_xor_sync(0xffffffffu, s, 1);
    int g = batch[node];
    if ((unsigned)g < (unsigned)MAXG) {
        atomic_add_v4((float4*)(g_pooled + g * HD) + l, v);
        if (l == 0) atomicAdd(&g_counts[g], 1.0f);
    }
    if (l == 0) out[node] = s + ba[0];
}

// ---- value head ----
__global__ void k_value(const float* __restrict__ Wc, const float* __restrict__ bc,
                        float* __restrict__ out, int n) {
    int g = blockIdx.x, lane = threadIdx.x;
    float s = g_pooled[g * HD + lane] * Wc[lane]
            + g_pooled[g * HD + 32 + lane] * Wc[32 + lane];
    s += __shfl_xor_sync(0xffffffffu, s, 16);
    s += __shfl_xor_sync(0xffffffffu, s, 8);
    s += __shfl_xor_sync(0xffffffffu, s, 4);
    s += __shfl_xor_sync(0xffffffffu, s, 2);
    s += __shfl_xor_sync(0xffffffffu, s, 1);
    if (lane == 0)
        out[n + g] = s / fmaxf(g_counts[g], 1.0f) + bc[0];
}

extern "C" void kernel_launch(void* const* d_in, const int* in_sizes, int n_in,
                              void* d_out, int out_size) {
    const float* x     = (const float*)d_in[0];
    const int*   ei    = (const int*)d_in[1];      // int32 (JAX x64 disabled)
    const int*   batch = (const int*)d_in[2];      // int32
    const float* W1    = (const float*)d_in[3];
    const float* b1    = (const float*)d_in[4];
    const float* W2    = (const float*)d_in[5];
    const float* b2    = (const float*)d_in[6];
    const float* Wa    = (const float*)d_in[7];
    const float* ba    = (const float*)d_in[8];
    const float* Wc    = (const float*)d_in[9];
    const float* bc    = (const float*)d_in[10];
    float* out = (float*)d_out;

    int n = in_sizes[2];
    int E = in_sizes[1] / 2;
    int G = out_size - n;   // = 64
    int nb = (n + SCB - 1) / SCB;

    // ---- CSR build + norms ----
    k_zero<<<(n + 255) / 256, 256>>>(n);
    k_hist<<<(E + 255) / 256, 256>>>(ei, E, n);
    k_scan1<<<nb, SCB>>>(n);
    k_scan2<<<1, 256>>>(nb);
    k_scan3<<<(n + 255) / 256, 256>>>(n);
    k_fill<<<(E + 255) / 256, 256>>>(ei, E, n);

    // ---- layer 1 ----
    k_gemm<128, false><<<(n + 63) / 64, 256>>>(x, W1, n);
    k_gather<<<(n * 16 + 255) / 256, 256>>>(b1, n);

    // ---- layer 2 (ReLU fused into GEMM input load) ----
    k_gemm<64, true><<<(n + 63) / 64, 256>>>(x /*unused*/, W2, n);
    k_gather<<<(n * 16 + 255) / 256, 256>>>(b2, n);

    // ---- heads ----
    k_final<<<(n * 16 + 255) / 256, 256>>>(batch, Wa, ba, out, n);
    if (G > 0) k_value<<<G, 32>>>(Wc, bc, out, n);
}

// round 11
// speedup vs baseline: 1.6981x; 1.0882x over previous
#include <cuda_runtime.h>

// GNNPolicy: 2-layer GCN + node logits head + graph mean-pool value head.
// CSR-gather aggregation + smem-staged tiled GEMMs.
// Inputs (metadata order): x[N,128] f32, edge_index[2,E] int32, batch[N] int32,
//   W1[128,64], b1[64], W2[64,64], b2[64], Wa[64,1], ba[1], Wc[64,1], bc[1]
// Output: concat(action_logits[N], value[G]) as float32, out_size = N + G.

#define HD 64
#define MAXN 100000
#define MAXE 1600000
#define MAXG 64
#define SCB  1024   // scan block width

// ---- scratch ----
__device__ __align__(16) int   g_cnt[MAXN];      // in-degree (dst), no self-loop
__device__ __align__(16) int   g_rowptr[MAXN];   // CSR row starts
__device__ __align__(16) int   g_cursor[MAXN];   // fill cursors
__device__ __align__(16) int   g_csrc[MAXE];     // CSR: src per (dst-sorted) edge
__device__ __align__(16) int   g_bsum[256];      // scan block sums
__device__ __align__(16) float g_dinv[MAXN];
__device__ __align__(16) float g_T[(size_t)MAXN * HD];    // Tp = (X@W) * dinv[row]
__device__ __align__(16) float g_AGG[(size_t)MAXN * HD];  // aggregated features
__device__ __align__(16) float g_pooled[MAXG * HD];
__device__ __align__(16) float g_counts[MAXG];

__device__ __forceinline__ void atomic_add_v4(float4* addr, float4 v) {
#if defined(__CUDA_ARCH__) && (__CUDA_ARCH__ >= 900)
    atomicAdd(addr, v);
#else
    float* a = (float*)addr;
    atomicAdd(a + 0, v.x); atomicAdd(a + 1, v.y);
    atomicAdd(a + 2, v.z); atomicAdd(a + 3, v.w);
#endif
}

// ---- zero: cnt, pooled, counts ----
__global__ void k_zero(int n) {
    int i = blockIdx.x * blockDim.x + threadIdx.x;
    if (i < n) g_cnt[i] = 0;
    if (i < MAXG * HD) g_pooled[i] = 0.0f;
    if (i < MAXG) g_counts[i] = 0.0f;
}

// ---- histogram over dst ----
__global__ void k_hist(const int* __restrict__ ei, int E, int n) {
    int e = blockIdx.x * blockDim.x + threadIdx.x;
    if (e < E) {
        int dst = ei[E + e];
        if ((unsigned)dst < (unsigned)n) atomicAdd(&g_cnt[dst], 1);
    }
}

// ---- scan level 1: per-block exclusive scan of cnt ----
__global__ void k_scan1(int n) {
    __shared__ int s[SCB];
    int t = threadIdx.x;
    int i = blockIdx.x * SCB + t;
    int v = (i < n) ? g_cnt[i] : 0;
    s[t] = v;
    __syncthreads();
#pragma unroll
    for (int off = 1; off < SCB; off <<= 1) {
        int x = (t >= off) ? s[t - off] : 0;
        __syncthreads();
        s[t] += x;
        __syncthreads();
    }
    if (i < n) g_rowptr[i] = s[t] - v;
    if (t == SCB - 1) g_bsum[blockIdx.x] = s[t];
}

// ---- scan level 2: exclusive scan of block totals ----
__global__ void k_scan2(int nb) {
    __shared__ int s[256];
    int t = threadIdx.x;
    int v = (t < nb) ? g_bsum[t] : 0;
    s[t] = v;
    __syncthreads();
#pragma unroll
    for (int off = 1; off < 256; off <<= 1) {
        int x = (t >= off) ? s[t - off] : 0;
        __syncthreads();
        s[t] += x;
        __syncthreads();
    }
    if (t < nb) g_bsum[t] = s[t] - v;
}

// ---- scan level 3: apply block offsets; init cursor; dinv ----
__global__ void k_scan3(int n) {
    int i = blockIdx.x * blockDim.x + threadIdx.x;
    if (i < n) {
        int rp = g_rowptr[i] + g_bsum[i >> 10];
        g_rowptr[i] = rp;
        g_cursor[i] = rp;
        g_dinv[i]   = rsqrtf((float)(g_cnt[i] + 1));
    }
}

// ---- fill CSR ----
__global__ void k_fill(const int* __restrict__ ei, int E, int n) {
    int e = blockIdx.x * blockDim.x + threadIdx.x;
    if (e < E) {
        int src = ei[e];
        int dst = ei[E + e];
        if ((unsigned)src < (unsigned)n && (unsigned)dst < (unsigned)n) {
            int pos = atomicAdd(&g_cursor[dst], 1);
            g_csrc[pos] = src;
        }
    }
}

// ---- GEMM: Tp = act(X) @ W * dinv[row]   [n,K]x[K,64]
// Smem-staged: X tile [64][K] loaded coalesced (float4), W transposed [64][K].
// Both padded to K+4 floats/row. 8 warps, 8 rows/warp, lane owns cols {c,c+32}.
// USE_AGG: X = g_AGG with ReLU fused at tile load.
template<int K, bool USE_AGG>
__global__ void k_gemm(const float* __restrict__ Xin, const float* __restrict__ W,
                       int n) {
    extern __shared__ __align__(16) float sm[];
    float* Wt = sm;                       // [64][K+4]
    float* Xs = sm + HD * (K + 4);        // [64][K+4]
    const float* X = USE_AGG ? (const float*)g_AGG : Xin;
    const int NF4 = K / 4;

    int tid = threadIdx.x;
    int row0 = blockIdx.x * 64;

    // W transpose into smem
    for (int idx = tid; idx < K * HD; idx += 256) {
        int k = idx >> 6, c = idx & 63;          // W row-major [K][64]
        Wt[c * (K + 4) + k] = W[idx];
    }
    // X tile, coalesced float4
    for (int i = tid; i < 64 * NF4; i += 256) {
        int r = i / NF4, c = i % NF4;
        int rr = row0 + r;
        float4 v = make_float4(0.f, 0.f, 0.f, 0.f);
        if (rr < n) v = ((const float4*)X)[(size_t)rr * NF4 + c];
        if (USE_AGG) {
            v.x = fmaxf(v.x, 0.0f); v.y = fmaxf(v.y, 0.0f);
            v.z = fmaxf(v.z, 0.0f); v.w = fmaxf(v.w, 0.0f);
        }
        *(float4*)&Xs[r * (K + 4) + c * 4] = v;
    }
    __syncthreads();

    int warp = tid >> 5, lane = tid & 31;
    const float* wt0 = &Wt[lane * (K + 4)];
    const float* wt1 = &Wt[(lane + 32) * (K + 4)];
    const float* xr0 = &Xs[(warp * 8) * (K + 4)];

    float acc0[8], acc1[8];
#pragma unroll
    for (int r = 0; r < 8; r++) { acc0[r] = 0.0f; acc1[r] = 0.0f; }

#pragma unroll 4
    for (int k = 0; k < K; k += 4) {
        float4 wa = *(const float4*)(wt0 + k);
        float4 wb = *(const float4*)(wt1 + k);
#pragma unroll
        for (int r = 0; r < 8; r++) {
            float4 xv = *(const float4*)(xr0 + r * (K + 4) + k);   // smem broadcast
            acc0[r] += xv.x * wa.x + xv.y * wa.y + xv.z * wa.z + xv.w * wa.w;
            acc1[r] += xv.x * wb.x + xv.y * wb.y + xv.z * wb.z + xv.w * wb.w;
        }
    }

    int rbase = row0 + warp * 8;
#pragma unroll
    for (int r = 0; r < 8; r++) {
        int rr = rbase + r;
        if (rr < n) {
            float di = g_dinv[rr];
            g_T[(size_t)rr * HD + lane]      = acc0[r] * di;
            g_T[(size_t)rr * HD + lane + 32] = acc1[r] * di;
        }
    }
}

// ---- gather: AGG[v] = b + dinv[v] * (Tp[v] + sum_{src in row v} Tp[src]) ----
__global__ void k_gather(const float* __restrict__ b, int n) {
    int tid = blockIdx.x * blockDim.x + threadIdx.x;
    int v = tid >> 4;
    if (v >= n) return;
    int l = tid & 15;
    int start = g_rowptr[v];
    int cnt   = g_cnt[v];
    float4 s = ((const float4*)(g_T + (size_t)v * HD))[l];   // self loop (Tp[v])
    int u = (cnt > 0) ? g_csrc[start] : 0;
    for (int j = 0; j < cnt; j++) {
        int un = (j + 1 < cnt) ? g_csrc[start + j + 1] : 0;  // prefetch next idx
        float4 t = ((const float4*)(g_T + (size_t)u * HD))[l];
        s.x += t.x; s.y += t.y; s.z += t.z; s.w += t.w;
        u = un;
    }
    float dv = g_dinv[v];
    float4 bb = ((const float4*)b)[l];
    float4 o;
    o.x = bb.x + dv * s.x; o.y = bb.y + dv * s.y;
    o.z = bb.z + dv * s.z; o.w = bb.w + dv * s.w;
    ((float4*)(g_AGG + (size_t)v * HD))[l] = o;
}

// ---- finalize: relu, logits = h2.Wa + ba, mean-pool scatter ----
__global__ void k_final(const int* __restrict__ batch, const float* __restrict__ Wa,
                        const float* __restrict__ ba, float* __restrict__ out, int n) {
    int tid = blockIdx.x * blockDim.x + threadIdx.x;
    int node = tid >> 4;
    if (node >= n) return;
    int l = tid & 15;
    float4 v = ((const float4*)(g_AGG + (size_t)node * HD))[l];
    v.x = fmaxf(v.x, 0.0f); v.y = fmaxf(v.y, 0.0f);
    v.z = fmaxf(v.z, 0.0f); v.w = fmaxf(v.w, 0.0f);
    float4 wa = ((const float4*)Wa)[l];
    float s = v.x * wa.x + v.y * wa.y + v.z * wa.z + v.w * wa.w;
    s += __shfl_xor_sync(0xffffffffu, s, 8);
    s += __shfl_xor_sync(0xffffffffu, s, 4);
    s += __shfl_xor_sync(0xffffffffu, s, 2);
    s += __shfl_xor_sync(0xffffffffu, s, 1);
    int g = batch[node];
    if ((unsigned)g < (unsigned)MAXG) {
        atomic_add_v4((float4*)(g_pooled + g * HD) + l, v);
        if (l == 0) atomicAdd(&g_counts[g], 1.0f);
    }
    if (l == 0) out[node] = s + ba[0];
}

// ---- value head ----
__global__ void k_value(const float* __restrict__ Wc, const float* __restrict__ bc,
                        float* __restrict__ out, int n) {
    int g = blockIdx.x, lane = threadIdx.x;
    float s = g_pooled[g * HD + lane] * Wc[lane]
            + g_pooled[g * HD + 32 + lane] * Wc[32 + lane];
    s += __shfl_xor_sync(0xffffffffu, s, 16);
    s += __shfl_xor_sync(0xffffffffu, s, 8);
    s += __shfl_xor_sync(0xffffffffu, s, 4);
    s += __shfl_xor_sync(0xffffffffu, s, 2);
    s += __shfl_xor_sync(0xffffffffu, s, 1);
    if (lane == 0)
        out[n + g] = s / fmaxf(g_counts[g], 1.0f) + bc[0];
}

extern "C" void kernel_launch(void* const* d_in, const int* in_sizes, int n_in,
                              void* d_out, int out_size) {
    const float* x     = (const float*)d_in[0];
    const int*   ei    = (const int*)d_in[1];      // int32 (JAX x64 disabled)
    const int*   batch = (const int*)d_in[2];      // int32
    const float* W1    = (const float*)d_in[3];
    const float* W2    = (const float*)d_in[5];
    const float* b1    = (const float*)d_in[4];
    const float* b2    = (const float*)d_in[6];
    const float* Wa    = (const float*)d_in[7];
    const float* ba    = (const float*)d_in[8];
    const float* Wc    = (const float*)d_in[9];
    const float* bc    = (const float*)d_in[10];
    float* out = (float*)d_out;

    int n = in_sizes[2];
    int E = in_sizes[1] / 2;
    int G = out_size - n;   // = 64
    int nb = (n + SCB - 1) / SCB;

    // dynamic smem sizes: 2 tiles of [64][K+4] floats
    int smem1 = 2 * HD * (128 + 4) * sizeof(float);   // 67584
    int smem2 = 2 * HD * (64 + 4) * sizeof(float);    // 34816
    static int attr_done = 0;
    if (!attr_done) {
        cudaFuncSetAttribute(k_gemm<128, false>,
                             cudaFuncAttributeMaxDynamicSharedMemorySize, smem1);
        cudaFuncSetAttribute(k_gemm<64, true>,
                             cudaFuncAttributeMaxDynamicSharedMemorySize, smem2);
        attr_done = 1;
    }

    // ---- CSR build + norms ----
    k_zero<<<(n + 255) / 256, 256>>>(n);
    k_hist<<<(E + 255) / 256, 256>>>(ei, E, n);
    k_scan1<<<nb, SCB>>>(n);
    k_scan2<<<1, 256>>>(nb);
    k_scan3<<<(n + 255) / 256, 256>>>(n);
    k_fill<<<(E + 255) / 256, 256>>>(ei, E, n);

    // ---- layer 1 ----
    k_gemm<128, false><<<(n + 63) / 64, 256, smem1>>>(x, W1, n);
    k_gather<<<(n * 16 + 255) / 256, 256>>>(b1, n);

    // ---- layer 2 (ReLU fused into tile load) ----
    k_gemm<64, true><<<(n + 63) / 64, 256, smem2>>>(x /*unused*/, W2, n);
    k_gather<<<(n * 16 + 255) / 256, 256>>>(b2, n);

    // ---- heads ----
    k_final<<<(n * 16 + 255) / 256, 256>>>(batch, Wa, ba, out, n);
    if (G > 0) k_value<<<G, 32>>>(Wc, bc, out, n);
}

// round 12
// speedup vs baseline: 1.8534x; 1.0915x over previous
#include <cuda_runtime.h>

// GNNPolicy: 2-layer GCN + node logits head + graph mean-pool value head.
// CSR-gather aggregation, smem-staged GEMMs, stream-forked GEMM1 || CSR build,
// gather1+GEMM2 fused (agg1 never materialized), gather2+heads fused.
// Inputs: x[N,128] f32, edge_index[2,E] int32, batch[N] int32,
//   W1[128,64], b1[64], W2[64,64], b2[64], Wa[64,1], ba[1], Wc[64,1], bc[1]
// Output: concat(action_logits[N], value[G]) as float32, out_size = N + G.

#define HD 64
#define MAXN 100000
#define MAXE 1600000
#define MAXG 64
#define SCB  1024   // scan block width

// ---- scratch ----
__device__ __align__(16) int   g_cnt[MAXN];      // in-degree (dst), no self-loop
__device__ __align__(16) int   g_rowptr[MAXN];   // CSR row starts
__device__ __align__(16) int   g_cursor[MAXN];   // fill cursors
__device__ __align__(16) int   g_csrc[MAXE];     // CSR: src per (dst-sorted) edge
__device__ __align__(16) int   g_bsum[256];      // scan block sums
__device__ __align__(16) float g_dinv[MAXN];
__device__ __align__(16) float g_T[(size_t)MAXN * HD];    // layer1: raw X@W1
__device__ __align__(16) float g_T2[(size_t)MAXN * HD];   // layer2: (relu(agg1)@W2)*dinv
__device__ __align__(16) float g_pooled[MAXG * HD];
__device__ __align__(16) float g_counts[MAXG];

__device__ __forceinline__ void atomic_add_v4(float4* addr, float4 v) {
#if defined(__CUDA_ARCH__) && (__CUDA_ARCH__ >= 900)
    atomicAdd(addr, v);
#else
    float* a = (float*)addr;
    atomicAdd(a + 0, v.x); atomicAdd(a + 1, v.y);
    atomicAdd(a + 2, v.z); atomicAdd(a + 3, v.w);
#endif
}

// ---- zero: cnt, pooled, counts ----
__global__ void k_zero(int n) {
    int i = blockIdx.x * blockDim.x + threadIdx.x;
    if (i < n) g_cnt[i] = 0;
    if (i < MAXG * HD) g_pooled[i] = 0.0f;
    if (i < MAXG) g_counts[i] = 0.0f;
}

// ---- histogram over dst ----
__global__ void k_hist(const int* __restrict__ ei, int E, int n) {
    int e = blockIdx.x * blockDim.x + threadIdx.x;
    if (e < E) {
        int dst = ei[E + e];
        if ((unsigned)dst < (unsigned)n) atomicAdd(&g_cnt[dst], 1);
    }
}

// ---- scan level 1 ----
__global__ void k_scan1(int n) {
    __shared__ int s[SCB];
    int t = threadIdx.x;
    int i = blockIdx.x * SCB + t;
    int v = (i < n) ? g_cnt[i] : 0;
    s[t] = v;
    __syncthreads();
#pragma unroll
    for (int off = 1; off < SCB; off <<= 1) {
        int x = (t >= off) ? s[t - off] : 0;
        __syncthreads();
        s[t] += x;
        __syncthreads();
    }
    if (i < n) g_rowptr[i] = s[t] - v;
    if (t == SCB - 1) g_bsum[blockIdx.x] = s[t];
}

// ---- scan level 2 ----
__global__ void k_scan2(int nb) {
    __shared__ int s[256];
    int t = threadIdx.x;
    int v = (t < nb) ? g_bsum[t] : 0;
    s[t] = v;
    __syncthreads();
#pragma unroll
    for (int off = 1; off < 256; off <<= 1) {
        int x = (t >= off) ? s[t - off] : 0;
        __syncthreads();
        s[t] += x;
        __syncthreads();
    }
    if (t < nb) g_bsum[t] = s[t] - v;
}

// ---- scan level 3: offsets, cursors, dinv ----
__global__ void k_scan3(int n) {
    int i = blockIdx.x * blockDim.x + threadIdx.x;
    if (i < n) {
        int rp = g_rowptr[i] + g_bsum[i >> 10];
        g_rowptr[i] = rp;
        g_cursor[i] = rp;
        g_dinv[i]   = rsqrtf((float)(g_cnt[i] + 1));
    }
}

// ---- fill CSR ----
__global__ void k_fill(const int* __restrict__ ei, int E, int n) {
    int e = blockIdx.x * blockDim.x + threadIdx.x;
    if (e < E) {
        int src = ei[e];
        int dst = ei[E + e];
        if ((unsigned)src < (unsigned)n && (unsigned)dst < (unsigned)n) {
            int pos = atomicAdd(&g_cursor[dst], 1);
            g_csrc[pos] = src;
        }
    }
}

// ---- GEMM1: T = X @ W1 (raw, NO dinv — runs concurrently with CSR build) ----
__global__ void k_gemm1(const float* __restrict__ X, const float* __restrict__ W,
                        int n) {
    const int K = 128;
    extern __shared__ __align__(16) float sm[];
    float* Wt = sm;                       // [64][132]
    float* Xs = sm + HD * (K + 4);        // [64][132]
    const int NF4 = K / 4;

    int tid = threadIdx.x;
    int row0 = blockIdx.x * 64;

    for (int idx = tid; idx < K * HD; idx += 256) {
        int k = idx >> 6, c = idx & 63;
        Wt[c * (K + 4) + k] = W[idx];
    }
    for (int i = tid; i < 64 * NF4; i += 256) {
        int r = i / NF4, c = i % NF4;
        int rr = row0 + r;
        float4 v = make_float4(0.f, 0.f, 0.f, 0.f);
        if (rr < n) v = ((const float4*)X)[(size_t)rr * NF4 + c];
        *(float4*)&Xs[r * (K + 4) + c * 4] = v;
    }
    __syncthreads();

    int warp = tid >> 5, lane = tid & 31;
    const float* wt0 = &Wt[lane * (K + 4)];
    const float* wt1 = &Wt[(lane + 32) * (K + 4)];
    const float* xr0 = &Xs[(warp * 8) * (K + 4)];

    float acc0[8], acc1[8];
#pragma unroll
    for (int r = 0; r < 8; r++) { acc0[r] = 0.0f; acc1[r] = 0.0f; }

#pragma unroll 4
    for (int k = 0; k < K; k += 4) {
        float4 wa = *(const float4*)(wt0 + k);
        float4 wb = *(const float4*)(wt1 + k);
#pragma unroll
        for (int r = 0; r < 8; r++) {
            float4 xv = *(const float4*)(xr0 + r * (K + 4) + k);
            acc0[r] += xv.x * wa.x + xv.y * wa.y + xv.z * wa.z + xv.w * wa.w;
            acc1[r] += xv.x * wb.x + xv.y * wb.y + xv.z * wb.z + xv.w * wb.w;
        }
    }

    int rbase = row0 + warp * 8;
#pragma unroll
    for (int r = 0; r < 8; r++) {
        int rr = rbase + r;
        if (rr < n) {
            g_T[(size_t)rr * HD + lane]      = acc0[r];
            g_T[(size_t)rr * HD + lane + 32] = acc1[r];
        }
    }
}

// ---- fused gather1 + GEMM2 ----
// Phase 1: agg1[v] = relu(b1 + dinv[v]*(T[v]*dinv[v] + sum_u T[u]*dinv[u]))
//          written straight into the smem X tile (never hits global).
// Phase 2: T2 = agg1_tile @ W2 * dinv[row] -> g_T2.
__global__ void k_fuse1(const float* __restrict__ W2, const float* __restrict__ b1,
                        int n) {
    const int K = 64;
    extern __shared__ __align__(16) float sm[];
    float* Wt = sm;                       // [64][68]
    float* Xs = sm + HD * (K + 4);        // [64][68]

    int tid = threadIdx.x;
    int row0 = blockIdx.x * 64;

    for (int idx = tid; idx < K * HD; idx += 256) {
        int k = idx >> 6, c = idx & 63;
        Wt[c * (K + 4) + k] = W2[idx];
    }

    // gather phase: 16 nodes in flight (16 lanes each), 4 passes
    int l = tid & 15;
    float4 bb = ((const float4*)b1)[l];
#pragma unroll
    for (int it = 0; it < 4; it++) {
        int r = it * 16 + (tid >> 4);
        int v = row0 + r;
        float4 s = make_float4(0.f, 0.f, 0.f, 0.f);
        if (v < n) {
            float dv = g_dinv[v];
            float4 t = ((const float4*)(g_T + (size_t)v * HD))[l];
            s.x = t.x * dv; s.y = t.y * dv; s.z = t.z * dv; s.w = t.w * dv;
            int start = g_rowptr[v];
            int cnt   = g_cnt[v];
            int u = (cnt > 0) ? g_csrc[start] : 0;
            for (int j = 0; j < cnt; j++) {
                int un = (j + 1 < cnt) ? g_csrc[start + j + 1] : 0;
                float du = g_dinv[u];
                float4 tu = ((const float4*)(g_T + (size_t)u * HD))[l];
                s.x += tu.x * du; s.y += tu.y * du;
                s.z += tu.z * du; s.w += tu.w * du;
                u = un;
            }
            s.x = fmaxf(dv * s.x + bb.x, 0.0f);
            s.y = fmaxf(dv * s.y + bb.y, 0.0f);
            s.z = fmaxf(dv * s.z + bb.z, 0.0f);
            s.w = fmaxf(dv * s.w + bb.w, 0.0f);
        }
        *(float4*)&Xs[r * (K + 4) + l * 4] = s;
    }
    __syncthreads();

    // GEMM phase
    int warp = tid >> 5, lane = tid & 31;
    const float* wt0 = &Wt[lane * (K + 4)];
    const float* wt1 = &Wt[(lane + 32) * (K + 4)];
    const float* xr0 = &Xs[(warp * 8) * (K + 4)];

    float acc0[8], acc1[8];
#pragma unroll
    for (int r = 0; r < 8; r++) { acc0[r] = 0.0f; acc1[r] = 0.0f; }

#pragma unroll 4
    for (int k = 0; k < K; k += 4) {
        float4 wa = *(const float4*)(wt0 + k);
        float4 wb = *(const float4*)(wt1 + k);
#pragma unroll
        for (int r = 0; r < 8; r++) {
            float4 xv = *(const float4*)(xr0 + r * (K + 4) + k);
            acc0[r] += xv.x * wa.x + xv.y * wa.y + xv.z * wa.z + xv.w * wa.w;
            acc1[r] += xv.x * wb.x + xv.y * wb.y + xv.z * wb.z + xv.w * wb.w;
        }
    }

    int rbase = row0 + warp * 8;
#pragma unroll
    for (int r = 0; r < 8; r++) {
        int rr = rbase + r;
        if (rr < n) {
            float di = g_dinv[rr];
            g_T2[(size_t)rr * HD + lane]      = acc0[r] * di;
            g_T2[(size_t)rr * HD + lane + 32] = acc1[r] * di;
        }
    }
}

// ---- fused gather2 + heads: h2 = relu(b2 + dinv[v]*(T2p[v] + sum T2p[u]));
// logits = h2.Wa + ba; mean-pool scatter. agg2 never materialized.
__global__ void k_fuse2(const float* __restrict__ b2, const int* __restrict__ batch,
                        const float* __restrict__ Wa, const float* __restrict__ ba,
                        float* __restrict__ out, int n) {
    int tid = blockIdx.x * blockDim.x + threadIdx.x;
    int v = tid >> 4;
    if (v >= n) return;
    int l = tid & 15;
    int start = g_rowptr[v];
    int cnt   = g_cnt[v];
    float4 s = ((const float4*)(g_T2 + (size_t)v * HD))[l];   // self (premult dinv)
    int u = (cnt > 0) ? g_csrc[start] : 0;
    for (int j = 0; j < cnt; j++) {
        int un = (j + 1 < cnt) ? g_csrc[start + j + 1] : 0;
        float4 t = ((const float4*)(g_T2 + (size_t)u * HD))[l];
        s.x += t.x; s.y += t.y; s.z += t.z; s.w += t.w;
        u = un;
    }
    float dv = g_dinv[v];
    float4 bb = ((const float4*)b2)[l];
    float4 h;
    h.x = fmaxf(bb.x + dv * s.x, 0.0f);
    h.y = fmaxf(bb.y + dv * s.y, 0.0f);
    h.z = fmaxf(bb.z + dv * s.z, 0.0f);
    h.w = fmaxf(bb.w + dv * s.w, 0.0f);

    float4 wa = ((const float4*)Wa)[l];
    float sl = h.x * wa.x + h.y * wa.y + h.z * wa.z + h.w * wa.w;
    sl += __shfl_xor_sync(0xffffffffu, sl, 8);
    sl += __shfl_xor_sync(0xffffffffu, sl, 4);
    sl += __shfl_xor_sync(0xffffffffu, sl, 2);
    sl += __shfl_xor_sync(0xffffffffu, sl, 1);

    int g = batch[v];
    if ((unsigned)g < (unsigned)MAXG) {
        atomic_add_v4((float4*)(g_pooled + g * HD) + l, h);
        if (l == 0) atomicAdd(&g_counts[g], 1.0f);
    }
    if (l == 0) out[v] = sl + ba[0];
}

// ---- value head ----
__global__ void k_value(const float* __restrict__ Wc, const float* __restrict__ bc,
                        float* __restrict__ out, int n) {
    int g = blockIdx.x, lane = threadIdx.x;
    float s = g_pooled[g * HD + lane] * Wc[lane]
            + g_pooled[g * HD + 32 + lane] * Wc[32 + lane];
    s += __shfl_xor_sync(0xffffffffu, s, 16);
    s += __shfl_xor_sync(0xffffffffu, s, 8);
    s += __shfl_xor_sync(0xffffffffu, s, 4);
    s += __shfl_xor_sync(0xffffffffu, s, 2);
    s += __shfl_xor_sync(0xffffffffu, s, 1);
    if (lane == 0)
        out[n + g] = s / fmaxf(g_counts[g], 1.0f) + bc[0];
}

extern "C" void kernel_launch(void* const* d_in, const int* in_sizes, int n_in,
                              void* d_out, int out_size) {
    const float* x     = (const float*)d_in[0];
    const int*   ei    = (const int*)d_in[1];      // int32 (JAX x64 disabled)
    const int*   batch = (const int*)d_in[2];      // int32
    const float* W1    = (const float*)d_in[3];
    const float* b1    = (const float*)d_in[4];
    const float* W2    = (const float*)d_in[5];
    const float* b2    = (const float*)d_in[6];
    const float* Wa    = (const float*)d_in[7];
    const float* ba    = (const float*)d_in[8];
    const float* Wc    = (const float*)d_in[9];
    const float* bc    = (const float*)d_in[10];
    float* out = (float*)d_out;

    int n = in_sizes[2];
    int E = in_sizes[1] / 2;
    int G = out_size - n;   // = 64
    int nb = (n + SCB - 1) / SCB;

    int smem1 = 2 * HD * (128 + 4) * sizeof(float);   // 67584 (GEMM1)
    int smemF = 2 * HD * (64 + 4) * sizeof(float);    // 34816 (fuse1)
    cudaFuncSetAttribute(k_gemm1, cudaFuncAttributeMaxDynamicSharedMemorySize, smem1);
    cudaFuncSetAttribute(k_fuse1, cudaFuncAttributeMaxDynamicSharedMemorySize, smemF);

    // ---- fork: GEMM1 on side stream, CSR build on main (capture) stream ----
    cudaStream_t s1;
    cudaStreamCreateWithFlags(&s1, cudaStreamNonBlocking);
    cudaEvent_t ev_fork, ev_join;
    cudaEventCreateWithFlags(&ev_fork, cudaEventDisableTiming);
    cudaEventCreateWithFlags(&ev_join, cudaEventDisableTiming);

    cudaEventRecord(ev_fork, 0);
    cudaStreamWaitEvent(s1, ev_fork, 0);
    k_gemm1<<<(n + 63) / 64, 256, smem1, s1>>>(x, W1, n);
    cudaEventRecord(ev_join, s1);

    // CSR build + norms (main stream)
    k_zero<<<(n + 255) / 256, 256>>>(n);
    k_hist<<<(E + 255) / 256, 256>>>(ei, E, n);
    k_scan1<<<nb, SCB>>>(n);
    k_scan2<<<1, 256>>>(nb);
    k_scan3<<<(n + 255) / 256, 256>>>(n);
    k_fill<<<(E + 255) / 256, 256>>>(ei, E, n);

    cudaStreamWaitEvent(0, ev_join, 0);   // join GEMM1

    // ---- layer1 gather + GEMM2 (fused) ----
    k_fuse1<<<(n + 63) / 64, 256, smemF>>>(W2, b1, n);

    // ---- layer2 gather + heads (fused) ----
    k_fuse2<<<(n * 16 + 255) / 256, 256>>>(b2, batch, Wa, ba, out, n);
    if (G > 0) k_value<<<G, 32>>>(Wc, bc, out, n);

    cudaEventDestroy(ev_fork);
    cudaEventDestroy(ev_join);
    cudaStreamDestroy(s1);
}

// round 13
// speedup vs baseline: 1.8823x; 1.0156x over previous
#include <cuda_runtime.h>

// GNNPolicy: 2-layer GCN + node logits head + graph mean-pool value head.
// CSR-gather aggregation, smem-staged GEMMs with packed f32x2 FMA (FFMA2),
// stream-forked GEMM1 || CSR build, gather1+GEMM2 fused, gather2+heads fused.
// Inputs: x[N,128] f32, edge_index[2,E] int32, batch[N] int32,
//   W1[128,64], b1[64], W2[64,64], b2[64], Wa[64,1], ba[1], Wc[64,1], bc[1]
// Output: concat(action_logits[N], value[G]) as float32, out_size = N + G.

#define HD 64
#define MAXN 100000
#define MAXE 1600000
#define MAXG 64
#define SCB  1024   // scan block width

typedef unsigned long long u64;

// ---- scratch ----
__device__ __align__(16) int   g_cnt[MAXN];      // in-degree (dst), no self-loop
__device__ __align__(16) int   g_rowptr[MAXN];   // CSR row starts
__device__ __align__(16) int   g_cursor[MAXN];   // fill cursors
__device__ __align__(16) int   g_csrc[MAXE];     // CSR: src per (dst-sorted) edge
__device__ __align__(16) int   g_bsum[256];      // scan block sums
__device__ __align__(16) float g_dinv[MAXN];
__device__ __align__(16) float g_T[(size_t)MAXN * HD];    // layer1: raw X@W1
__device__ __align__(16) float g_T2[(size_t)MAXN * HD];   // layer2: (relu(agg1)@W2)*dinv
__device__ __align__(16) float g_pooled[MAXG * HD];
__device__ __align__(16) float g_counts[MAXG];

// ---- packed f32x2 helpers (FFMA2: sm_103a dual-fp32 pipe, PTX-only) ----
__device__ __forceinline__ u64 pk2(float a, float b) {
    u64 r;
    asm("mov.b64 %0, {%1, %2};" : "=l"(r) : "f"(a), "f"(b));
    return r;
}
__device__ __forceinline__ void fma2(u64& d, u64 a, u64 b) {
    asm("fma.rn.f32x2 %0, %1, %2, %0;" : "+l"(d) : "l"(a), "l"(b));
}
__device__ __forceinline__ float hsum2(u64 v) {
    float x, y;
    asm("mov.b64 {%0, %1}, %2;" : "=f"(x), "=f"(y) : "l"(v));
    return x + y;
}

__device__ __forceinline__ void atomic_add_v4(float4* addr, float4 v) {
#if defined(__CUDA_ARCH__) && (__CUDA_ARCH__ >= 900)
    atomicAdd(addr, v);
#else
    float* a = (float*)addr;
    atomicAdd(a + 0, v.x); atomicAdd(a + 1, v.y);
    atomicAdd(a + 2, v.z); atomicAdd(a + 3, v.w);
#endif
}

// ---- zero: cnt, pooled, counts ----
__global__ void k_zero(int n) {
    int i = blockIdx.x * blockDim.x + threadIdx.x;
    if (i < n) g_cnt[i] = 0;
    if (i < MAXG * HD) g_pooled[i] = 0.0f;
    if (i < MAXG) g_counts[i] = 0.0f;
}

// ---- histogram over dst ----
__global__ void k_hist(const int* __restrict__ ei, int E, int n) {
    int e = blockIdx.x * blockDim.x + threadIdx.x;
    if (e < E) {
        int dst = ei[E + e];
        if ((unsigned)dst < (unsigned)n) atomicAdd(&g_cnt[dst], 1);
    }
}

// ---- scan level 1 ----
__global__ void k_scan1(int n) {
    __shared__ int s[SCB];
    int t = threadIdx.x;
    int i = blockIdx.x * SCB + t;
    int v = (i < n) ? g_cnt[i] : 0;
    s[t] = v;
    __syncthreads();
#pragma unroll
    for (int off = 1; off < SCB; off <<= 1) {
        int x = (t >= off) ? s[t - off] : 0;
        __syncthreads();
        s[t] += x;
        __syncthreads();
    }
    if (i < n) g_rowptr[i] = s[t] - v;
    if (t == SCB - 1) g_bsum[blockIdx.x] = s[t];
}

// ---- scan level 2 ----
__global__ void k_scan2(int nb) {
    __shared__ int s[256];
    int t = threadIdx.x;
    int v = (t < nb) ? g_bsum[t] : 0;
    s[t] = v;
    __syncthreads();
#pragma unroll
    for (int off = 1; off < 256; off <<= 1) {
        int x = (t >= off) ? s[t - off] : 0;
        __syncthreads();
        s[t] += x;
        __syncthreads();
    }
    if (t < nb) g_bsum[t] = s[t] - v;
}

// ---- scan level 3: offsets, cursors, dinv ----
__global__ void k_scan3(int n) {
    int i = blockIdx.x * blockDim.x + threadIdx.x;
    if (i < n) {
        int rp = g_rowptr[i] + g_bsum[i >> 10];
        g_rowptr[i] = rp;
        g_cursor[i] = rp;
        g_dinv[i]   = rsqrtf((float)(g_cnt[i] + 1));
    }
}

// ---- fill CSR ----
__global__ void k_fill(const int* __restrict__ ei, int E, int n) {
    int e = blockIdx.x * blockDim.x + threadIdx.x;
    if (e < E) {
        int src = ei[e];
        int dst = ei[E + e];
        if ((unsigned)src < (unsigned)n && (unsigned)dst < (unsigned)n) {
            int pos = atomicAdd(&g_cursor[dst], 1);
            g_csrc[pos] = src;
        }
    }
}

// ---- GEMM1: T = X @ W1 (raw, NO dinv — runs concurrently with CSR build) ----
__global__ void k_gemm1(const float* __restrict__ X, const float* __restrict__ W,
                        int n) {
    const int K = 128;
    extern __shared__ __align__(16) float sm[];
    float* Wt = sm;                       // [64][132]
    float* Xs = sm + HD * (K + 4);        // [64][132]
    const int NF4 = K / 4;

    int tid = threadIdx.x;
    int row0 = blockIdx.x * 64;

    for (int idx = tid; idx < K * HD; idx += 256) {
        int k = idx >> 6, c = idx & 63;
        Wt[c * (K + 4) + k] = W[idx];
    }
    for (int i = tid; i < 64 * NF4; i += 256) {
        int r = i / NF4, c = i % NF4;
        int rr = row0 + r;
        float4 v = make_float4(0.f, 0.f, 0.f, 0.f);
        if (rr < n) v = ((const float4*)X)[(size_t)rr * NF4 + c];
        *(float4*)&Xs[r * (K + 4) + c * 4] = v;
    }
    __syncthreads();

    int warp = tid >> 5, lane = tid & 31;
    const float* wt0 = &Wt[lane * (K + 4)];
    const float* wt1 = &Wt[(lane + 32) * (K + 4)];
    const float* xr0 = &Xs[(warp * 8) * (K + 4)];

    u64 acc0[8], acc1[8];
#pragma unroll
    for (int r = 0; r < 8; r++) { acc0[r] = 0ull; acc1[r] = 0ull; }

#pragma unroll 4
    for (int k = 0; k < K; k += 4) {
        float4 wa = *(const float4*)(wt0 + k);
        float4 wb = *(const float4*)(wt1 + k);
        u64 wa01 = pk2(wa.x, wa.y), wa23 = pk2(wa.z, wa.w);
        u64 wb01 = pk2(wb.x, wb.y), wb23 = pk2(wb.z, wb.w);
#pragma unroll
        for (int r = 0; r < 8; r++) {
            float4 xv = *(const float4*)(xr0 + r * (K + 4) + k);
            u64 x01 = pk2(xv.x, xv.y), x23 = pk2(xv.z, xv.w);
            fma2(acc0[r], x01, wa01); fma2(acc0[r], x23, wa23);
            fma2(acc1[r], x01, wb01); fma2(acc1[r], x23, wb23);
        }
    }

    int rbase = row0 + warp * 8;
#pragma unroll
    for (int r = 0; r < 8; r++) {
        int rr = rbase + r;
        if (rr < n) {
            g_T[(size_t)rr * HD + lane]      = hsum2(acc0[r]);
            g_T[(size_t)rr * HD + lane + 32] = hsum2(acc1[r]);
        }
    }
}

// ---- fused gather1 + GEMM2 (agg1 lives only in smem) ----
__global__ void k_fuse1(const float* __restrict__ W2, const float* __restrict__ b1,
                        int n) {
    const int K = 64;
    extern __shared__ __align__(16) float sm[];
    float* Wt = sm;                       // [64][68]
    float* Xs = sm + HD * (K + 4);        // [64][68]

    int tid = threadIdx.x;
    int row0 = blockIdx.x * 64;

    for (int idx = tid; idx < K * HD; idx += 256) {
        int k = idx >> 6, c = idx & 63;
        Wt[c * (K + 4) + k] = W2[idx];
    }

    // gather phase: 16 lanes/node, 16 nodes in flight, 4 passes
    int l = tid & 15;
    float4 bb = ((const float4*)b1)[l];
#pragma unroll
    for (int it = 0; it < 4; it++) {
        int r = it * 16 + (tid >> 4);
        int v = row0 + r;
        float4 s = make_float4(0.f, 0.f, 0.f, 0.f);
        if (v < n) {
            float dv = g_dinv[v];
            float4 t = ((const float4*)(g_T + (size_t)v * HD))[l];
            s.x = t.x * dv; s.y = t.y * dv; s.z = t.z * dv; s.w = t.w * dv;
            int start = g_rowptr[v];
            int cnt   = g_cnt[v];
            int u = (cnt > 0) ? g_csrc[start] : 0;
            for (int j = 0; j < cnt; j++) {
                int un = (j + 1 < cnt) ? g_csrc[start + j + 1] : 0;
                float du = g_dinv[u];
                float4 tu = ((const float4*)(g_T + (size_t)u * HD))[l];
                s.x += tu.x * du; s.y += tu.y * du;
                s.z += tu.z * du; s.w += tu.w * du;
                u = un;
            }
            s.x = fmaxf(dv * s.x + bb.x, 0.0f);
            s.y = fmaxf(dv * s.y + bb.y, 0.0f);
            s.z = fmaxf(dv * s.z + bb.z, 0.0f);
            s.w = fmaxf(dv * s.w + bb.w, 0.0f);
        }
        *(float4*)&Xs[r * (K + 4) + l * 4] = s;
    }
    __syncthreads();

    // GEMM phase (packed f32x2)
    int warp = tid >> 5, lane = tid & 31;
    const float* wt0 = &Wt[lane * (K + 4)];
    const float* wt1 = &Wt[(lane + 32) * (K + 4)];
    const float* xr0 = &Xs[(warp * 8) * (K + 4)];

    u64 acc0[8], acc1[8];
#pragma unroll
    for (int r = 0; r < 8; r++) { acc0[r] = 0ull; acc1[r] = 0ull; }

#pragma unroll 4
    for (int k = 0; k < K; k += 4) {
        float4 wa = *(const float4*)(wt0 + k);
        float4 wb = *(const float4*)(wt1 + k);
        u64 wa01 = pk2(wa.x, wa.y), wa23 = pk2(wa.z, wa.w);
        u64 wb01 = pk2(wb.x, wb.y), wb23 = pk2(wb.z, wb.w);
#pragma unroll
        for (int r = 0; r < 8; r++) {
            float4 xv = *(const float4*)(xr0 + r * (K + 4) + k);
            u64 x01 = pk2(xv.x, xv.y), x23 = pk2(xv.z, xv.w);
            fma2(acc0[r], x01, wa01); fma2(acc0[r], x23, wa23);
            fma2(acc1[r], x01, wb01); fma2(acc1[r], x23, wb23);
        }
    }

    int rbase = row0 + warp * 8;
#pragma unroll
    for (int r = 0; r < 8; r++) {
        int rr = rbase + r;
        if (rr < n) {
            float di = g_dinv[rr];
            g_T2[(size_t)rr * HD + lane]      = hsum2(acc0[r]) * di;
            g_T2[(size_t)rr * HD + lane + 32] = hsum2(acc1[r]) * di;
        }
    }
}

// ---- fused gather2 + heads ----
__global__ void k_fuse2(const float* __restrict__ b2, const int* __restrict__ batch,
                        const float* __restrict__ Wa, const float* __restrict__ ba,
                        float* __restrict__ out, int n) {
    int tid = blockIdx.x * blockDim.x + threadIdx.x;
    int v = tid >> 4;
    if (v >= n) return;
    int l = tid & 15;
    int start = g_rowptr[v];
    int cnt   = g_cnt[v];
    float4 s = ((const float4*)(g_T2 + (size_t)v * HD))[l];   // self (premult dinv)
    int u = (cnt > 0) ? g_csrc[start] : 0;
    for (int j = 0; j < cnt; j++) {
        int un = (j + 1 < cnt) ? g_csrc[start + j + 1] : 0;
        float4 t = ((const float4*)(g_T2 + (size_t)u * HD))[l];
        s.x += t.x; s.y += t.y; s.z += t.z; s.w += t.w;
        u = un;
    }
    float dv = g_dinv[v];
    float4 bb = ((const float4*)b2)[l];
    float4 h;
    h.x = fmaxf(bb.x + dv * s.x, 0.0f);
    h.y = fmaxf(bb.y + dv * s.y, 0.0f);
    h.z = fmaxf(bb.z + dv * s.z, 0.0f);
    h.w = fmaxf(bb.w + dv * s.w, 0.0f);

    float4 wa = ((const float4*)Wa)[l];
    float sl = h.x * wa.x + h.y * wa.y + h.z * wa.z + h.w * wa.w;
    sl += __shfl_xor_sync(0xffffffffu, sl, 8);
    sl += __shfl_xor_sync(0xffffffffu, sl, 4);
    sl += __shfl_xor_sync(0xffffffffu, sl, 2);
    sl += __shfl_xor_sync(0xffffffffu, sl, 1);

    int g = batch[v];
    if ((unsigned)g < (unsigned)MAXG) {
        atomic_add_v4((float4*)(g_pooled + g * HD) + l, h);
        if (l == 0) atomicAdd(&g_counts[g], 1.0f);
    }
    if (l == 0) out[v] = sl + ba[0];
}

// ---- value head ----
__global__ void k_value(const float* __restrict__ Wc, const float* __restrict__ bc,
                        float* __restrict__ out, int n) {
    int g = blockIdx.x, lane = threadIdx.x;
    float s = g_pooled[g * HD + lane] * Wc[lane]
            + g_pooled[g * HD + 32 + lane] * Wc[32 + lane];
    s += __shfl_xor_sync(0xffffffffu, s, 16);
    s += __shfl_xor_sync(0xffffffffu, s, 8);
    s += __shfl_xor_sync(0xffffffffu, s, 4);
    s += __shfl_xor_sync(0xffffffffu, s, 2);
    s += __shfl_xor_sync(0xffffffffu, s, 1);
    if (lane == 0)
        out[n + g] = s / fmaxf(g_counts[g], 1.0f) + bc[0];
}

extern "C" void kernel_launch(void* const* d_in, const int* in_sizes, int n_in,
                              void* d_out, int out_size) {
    const float* x     = (const float*)d_in[0];
    const int*   ei    = (const int*)d_in[1];      // int32 (JAX x64 disabled)
    const int*   batch = (const int*)d_in[2];      // int32
    const float* W1    = (const float*)d_in[3];
    const float* b1    = (const float*)d_in[4];
    const float* W2    = (const float*)d_in[5];
    const float* b2    = (const float*)d_in[6];
    const float* Wa    = (const float*)d_in[7];
    const float* ba    = (const float*)d_in[8];
    const float* Wc    = (const float*)d_in[9];
    const float* bc    = (const float*)d_in[10];
    float* out = (float*)d_out;

    int n = in_sizes[2];
    int E = in_sizes[1] / 2;
    int G = out_size - n;   // = 64
    int nb = (n + SCB - 1) / SCB;

    int smem1 = 2 * HD * (128 + 4) * sizeof(float);   // 67584 (GEMM1)
    int smemF = 2 * HD * (64 + 4) * sizeof(float);    // 34816 (fuse1)
    cudaFuncSetAttribute(k_gemm1, cudaFuncAttributeMaxDynamicSharedMemorySize, smem1);
    cudaFuncSetAttribute(k_fuse1, cudaFuncAttributeMaxDynamicSharedMemorySize, smemF);

    // ---- fork: GEMM1 on side stream, CSR build on main (capture) stream ----
    cudaStream_t s1;
    cudaStreamCreateWithFlags(&s1, cudaStreamNonBlocking);
    cudaEvent_t ev_fork, ev_join;
    cudaEventCreateWithFlags(&ev_fork, cudaEventDisableTiming);
    cudaEventCreateWithFlags(&ev_join, cudaEventDisableTiming);

    cudaEventRecord(ev_fork, 0);
    cudaStreamWaitEvent(s1, ev_fork, 0);
    k_gemm1<<<(n + 63) / 64, 256, smem1, s1>>>(x, W1, n);
    cudaEventRecord(ev_join, s1);

    // CSR build + norms (main stream)
    k_zero<<<(n + 255) / 256, 256>>>(n);
    k_hist<<<(E + 255) / 256, 256>>>(ei, E, n);
    k_scan1<<<nb, SCB>>>(n);
    k_scan2<<<1, 256>>>(nb);
    k_scan3<<<(n + 255) / 256, 256>>>(n);
    k_fill<<<(E + 255) / 256, 256>>>(ei, E, n);

    cudaStreamWaitEvent(0, ev_join, 0);   // join GEMM1

    // ---- layer1 gather + GEMM2 (fused) ----
    k_fuse1<<<(n + 63) / 64, 256, smemF>>>(W2, b1, n);

    // ---- layer2 gather + heads (fused) ----
    k_fuse2<<<(n * 16 + 255) / 256, 256>>>(b2, batch, Wa, ba, out, n);
    if (G > 0) k_value<<<G, 32>>>(Wc, bc, out, n);

    cudaEventDestroy(ev_fork);
    cudaEventDestroy(ev_join);
    cudaStreamDestroy(s1);
}